// round 2
// baseline (speedup 1.0000x reference)
#include <cuda_runtime.h>
#include <cuda_bf16.h>
#include <cstdint>

// ---------------- problem constants ----------------
#define BATCH  4
#define QLEN   1024
#define KLEN   2048
#define DMODEL 2048
#define FLEN   1025

#define INV_SQRT_FLEN 0.031234752f    // 1/sqrt(1025)
#define SCALE_OUT     0.022097087f    // 1/sqrt(2048)

// GEMM tiling (mma.sync path — tcgen05 not available at harness ptxas target)
#define BM 128
#define BN 128
#define BK 32
#define KITERS 36                     // banded K extent 1152 = 36*32
#define NTHREADS 256
#define TILE_BYTES  (128 * 64)        // 128 rows x 32 bf16 (64 B)
#define STAGE_BYTES (4 * TILE_BYTES)  // Ah, Al, Bh, Bl
#define SMEM_BYTES  (2 * STAGE_BYTES) // double buffered = 64 KB

// ---------------- device scratch (no allocations allowed) ----------------
__device__ __nv_bfloat16 g_ft_hi[(size_t)QLEN * KLEN];
__device__ __nv_bfloat16 g_ft_lo[(size_t)QLEN * KLEN];
__device__ __nv_bfloat16 g_xt_hi[(size_t)BATCH * DMODEL * KLEN];  // [b][d][k]
__device__ __nv_bfloat16 g_xt_lo[(size_t)BATCH * DMODEL * KLEN];

// ---------------- PTX helpers ----------------
__device__ __forceinline__ uint32_t smem_to_u32(const void* smem_ptr) {
    uint32_t addr;
    asm("{ .reg .u64 tmp; cvta.to.shared.u64 tmp, %1; cvt.u32.u64 %0, tmp; }"
        : "=r"(addr) : "l"(smem_ptr));
    return addr;
}

#define CP_ASYNC16(dst_u32, src_ptr) \
    asm volatile("cp.async.cg.shared.global [%0], [%1], 16;" \
                 :: "r"(dst_u32), "l"(src_ptr))

#define CP_COMMIT() asm volatile("cp.async.commit_group;" ::: "memory")
#define CP_WAIT1()  asm volatile("cp.async.wait_group 1;" ::: "memory")

#define LDSM_X4(r, addr) \
    asm volatile("ldmatrix.sync.aligned.m8n8.x4.shared.b16 {%0,%1,%2,%3}, [%4];" \
        : "=r"((r)[0]), "=r"((r)[1]), "=r"((r)[2]), "=r"((r)[3]) : "r"(addr))

#define MMA16816(c, a, b0, b1) \
    asm volatile("mma.sync.aligned.m16n8k16.row.col.f32.bf16.bf16.f32 " \
        "{%0,%1,%2,%3}, {%4,%5,%6,%7}, {%8,%9}, {%0,%1,%2,%3};" \
        : "+f"((c)[0]), "+f"((c)[1]), "+f"((c)[2]), "+f"((c)[3]) \
        : "r"((a)[0]), "r"((a)[1]), "r"((a)[2]), "r"((a)[3]), "r"(b0), "r"(b1))

// ---------------- kernel 1: build banded FT (hi/lo bf16 split) ----------------
// FT[l,k] = cos(2*pi*l*(k-l)/1025)/sqrt(1025) for l <= k <= l+1024, else 0.
__global__ void build_ft_kernel() {
    int idx = blockIdx.x * blockDim.x + threadIdx.x;
    if (idx >= QLEN * KLEN) return;
    int l = idx >> 11;
    int k = idx & (KLEN - 1);
    int j = k - l;
    float v = 0.0f;
    if (j >= 0 && j < FLEN) {
        int r = (l * j) % FLEN;                 // fits int32
        v = cospif(2.0f * (float)r / (float)FLEN) * INV_SQRT_FLEN;
    }
    __nv_bfloat16 hi = __float2bfloat16(v);
    float lof = v - __bfloat162float(hi);
    g_ft_hi[idx] = hi;
    g_ft_lo[idx] = __float2bfloat16(lof);
}

// ---------------- kernel 2: X = x (+p), transpose to [b][d][k], split hi/lo ---
__global__ void build_xt_kernel(const float* __restrict__ x,
                                const float* __restrict__ p,
                                const int* __restrict__ add_pos) {
    __shared__ float tile[32][33];
    int b  = blockIdx.z;
    int d0 = blockIdx.x * 32;
    int k0 = blockIdx.y * 32;
    int ap = *add_pos;
    const size_t base = (size_t)b * KLEN * DMODEL;

    #pragma unroll
    for (int i = threadIdx.y; i < 32; i += 8) {
        size_t g = base + (size_t)(k0 + i) * DMODEL + (d0 + threadIdx.x);
        float s = x[g];
        if (ap) s += p[g];
        tile[i][threadIdx.x] = s;
    }
    __syncthreads();
    #pragma unroll
    for (int i = threadIdx.y; i < 32; i += 8) {
        float s = tile[threadIdx.x][i];
        __nv_bfloat16 hi = __float2bfloat16(s);
        float lof = s - __bfloat162float(hi);
        size_t g = base + (size_t)(d0 + i) * KLEN + (k0 + threadIdx.x);
        g_xt_hi[g] = hi;
        g_xt_lo[g] = __float2bfloat16(lof);
    }
}

// ---------------- kernel 3: banded GEMM via mma.sync (3-product bf16 split) ---
// Smem stage layout: Ah @0, Al @8192, Bh @16384, Bl @24576 (each 128 x 64B,
// 16B chunks swizzled: chunk c stored at c ^ ((row>>1)&3)).
__global__ void __launch_bounds__(NTHREADS, 2)
gemm_kernel(float* __restrict__ out) {
    extern __shared__ char smem[];
    const uint32_t sbase = smem_to_u32(smem);
    const int tid  = threadIdx.x;
    const int lane = tid & 31;
    const int wid  = tid >> 5;
    const int wm   = wid & 1;    // 2 warps in M
    const int wn   = wid >> 1;   // 4 warps in N

    const int d0 = blockIdx.x * BN;
    const int m0 = blockIdx.y * BM;
    const int b  = blockIdx.z;

    // global tile base pointers (row r = tile row, k absolute)
    const __nv_bfloat16* tb0 = g_ft_hi + (size_t)m0 * KLEN;
    const __nv_bfloat16* tb1 = g_ft_lo + (size_t)m0 * KLEN;
    const __nv_bfloat16* tb2 = g_xt_hi + ((size_t)b * DMODEL + d0) * KLEN;
    const __nv_bfloat16* tb3 = g_xt_lo + ((size_t)b * DMODEL + d0) * KLEN;

    // ---- stage loader: 8 x 16B cp.async per thread ----
    auto load_stage = [&](int stage, int k0) {
        const __nv_bfloat16* bases[4] = {tb0, tb1, tb2, tb3};
        #pragma unroll
        for (int i = 0; i < 8; i++) {
            const int tile = i >> 1;                 // compile-time per unroll
            const int idx  = (i & 1) * 256 + tid;    // 0..511 within tile
            const int r    = idx >> 2;
            const int c    = idx & 3;
            const int csw  = c ^ ((r >> 1) & 3);
            uint32_t so = sbase + stage * STAGE_BYTES + tile * TILE_BYTES
                        + r * 64 + (csw << 4);
            const __nv_bfloat16* g = bases[tile] + (size_t)r * KLEN + k0 + c * 8;
            CP_ASYNC16(so, g);
        }
        CP_COMMIT();
    };

    float acc[4][4][4] = {};   // [mi][ni][4]

    load_stage(0, m0);         // band starts at k = m0

    for (int kt = 0; kt < KITERS; kt++) {
        if (kt + 1 < KITERS) load_stage((kt + 1) & 1, m0 + (kt + 1) * BK);
        else                 CP_COMMIT();          // empty group keeps wait math uniform
        CP_WAIT1();
        __syncthreads();

        const uint32_t sb = sbase + (kt & 1) * STAGE_BYTES;
        const int AOFF[3] = {0, 0, TILE_BYTES};                    // Ah, Ah, Al
        const int BOFF[3] = {2 * TILE_BYTES, 3 * TILE_BYTES, 2 * TILE_BYTES}; // Bh, Bl, Bh

        #pragma unroll
        for (int pidx = 0; pidx < 3; pidx++) {
            const uint32_t aoff = sb + AOFF[pidx];
            const uint32_t boff = sb + BOFF[pidx];
            #pragma unroll
            for (int ks = 0; ks < 2; ks++) {
                uint32_t af[4][4];
                uint32_t bfr[2][4];
                #pragma unroll
                for (int mi = 0; mi < 4; mi++) {
                    int row_s = wm * 64 + mi * 16 + (lane & 15);
                    int chunk = ks * 2 + (lane >> 4);
                    uint32_t addr = aoff + row_s * 64
                                  + ((chunk ^ ((row_s >> 1) & 3)) << 4);
                    LDSM_X4(af[mi], addr);
                }
                #pragma unroll
                for (int pr = 0; pr < 2; pr++) {
                    int g8    = lane >> 3;           // 0..3 matrix select
                    int ntile = pr * 2 + (g8 >> 1);
                    int khalf = g8 & 1;
                    int row_s = wn * 32 + ntile * 8 + (lane & 7);
                    int chunk = ks * 2 + khalf;
                    uint32_t addr = boff + row_s * 64
                                  + ((chunk ^ ((row_s >> 1) & 3)) << 4);
                    LDSM_X4(bfr[pr], addr);
                }
                #pragma unroll
                for (int mi = 0; mi < 4; mi++)
                    #pragma unroll
                    for (int ni = 0; ni < 4; ni++)
                        MMA16816(acc[mi][ni], af[mi],
                                 bfr[ni >> 1][(ni & 1) * 2],
                                 bfr[ni >> 1][(ni & 1) * 2 + 1]);
            }
        }
        __syncthreads();
    }

    // ---- epilogue: scale + float2 stores ----
    #pragma unroll
    for (int mi = 0; mi < 4; mi++) {
        #pragma unroll
        for (int ni = 0; ni < 4; ni++) {
            int row = m0 + wm * 64 + mi * 16 + (lane >> 2);
            int col = d0 + wn * 32 + ni * 8 + (lane & 3) * 2;
            float* o = out + ((size_t)b * QLEN + row) * DMODEL + col;
            float2 v0 = {acc[mi][ni][0] * SCALE_OUT, acc[mi][ni][1] * SCALE_OUT};
            float2 v1 = {acc[mi][ni][2] * SCALE_OUT, acc[mi][ni][3] * SCALE_OUT};
            *reinterpret_cast<float2*>(o) = v0;
            *reinterpret_cast<float2*>(o + 8 * DMODEL) = v1;
        }
    }
}

// ---------------- launch ----------------
extern "C" void kernel_launch(void* const* d_in, const int* in_sizes, int n_in,
                              void* d_out, int out_size) {
    const float* x = (const float*)d_in[0];
    const float* p = (const float*)d_in[1];
    // d_in[2] = qlen (fixed 1024 by problem shape), d_in[3] = add_position flag
    const int* add_pos = (const int*)d_in[3];
    float* out = (float*)d_out;

    cudaFuncSetAttribute(gemm_kernel,
                         cudaFuncAttributeMaxDynamicSharedMemorySize, SMEM_BYTES);

    build_ft_kernel<<<(QLEN * KLEN) / 256, 256>>>();
    build_xt_kernel<<<dim3(DMODEL / 32, KLEN / 32, BATCH), dim3(32, 8)>>>(x, p, add_pos);
    gemm_kernel<<<dim3(DMODEL / BN, QLEN / BM, BATCH), NTHREADS, SMEM_BYTES>>>(out);
}

// round 3
// speedup vs baseline: 2.0393x; 2.0393x over previous
#include <cuda_runtime.h>
#include <cuda_fp16.h>
#include <cstdint>

// ---------------- problem constants ----------------
#define BATCH  4
#define QLEN   1024
#define KLEN   2048
#define DMODEL 2048
#define FLEN   1025

#define INV_SQRT_FLEN 0.031234752f    // 1/sqrt(1025)
#define SCALE_OUT     0.022097087f    // 1/sqrt(2048)

// GEMM tiling (mma.sync fp16 path)
#define BM 128
#define BN 128
#define BK 32
#define KITERS 36                     // banded K extent 1152 = 36*32
#define NTHREADS 256
#define TILE_BYTES  (128 * 64)        // 128 rows x 32 fp16 (64 B)
#define STAGE_BYTES (2 * TILE_BYTES)  // A, B
#define NSTAGES 3
#define SMEM_BYTES  (NSTAGES * STAGE_BYTES)   // 48 KB

// ---------------- device scratch (no allocations allowed) ----------------
__device__ __half g_ft[(size_t)QLEN * KLEN];
__device__ __half g_xt[(size_t)BATCH * DMODEL * KLEN];   // [b][d][k]

// ---------------- PTX helpers ----------------
__device__ __forceinline__ uint32_t smem_to_u32(const void* smem_ptr) {
    uint32_t addr;
    asm("{ .reg .u64 tmp; cvta.to.shared.u64 tmp, %1; cvt.u32.u64 %0, tmp; }"
        : "=r"(addr) : "l"(smem_ptr));
    return addr;
}

#define CP_ASYNC16(dst_u32, src_ptr) \
    asm volatile("cp.async.cg.shared.global [%0], [%1], 16;" \
                 :: "r"(dst_u32), "l"(src_ptr))

#define CP_COMMIT() asm volatile("cp.async.commit_group;" ::: "memory")
#define CP_WAIT1()  asm volatile("cp.async.wait_group 1;" ::: "memory")

#define LDSM_X4(r, addr) \
    asm volatile("ldmatrix.sync.aligned.m8n8.x4.shared.b16 {%0,%1,%2,%3}, [%4];" \
        : "=r"((r)[0]), "=r"((r)[1]), "=r"((r)[2]), "=r"((r)[3]) : "r"(addr))

#define MMA16816(c, a, b0, b1) \
    asm volatile("mma.sync.aligned.m16n8k16.row.col.f32.f16.f16.f32 " \
        "{%0,%1,%2,%3}, {%4,%5,%6,%7}, {%8,%9}, {%0,%1,%2,%3};" \
        : "+f"((c)[0]), "+f"((c)[1]), "+f"((c)[2]), "+f"((c)[3]) \
        : "r"((a)[0]), "r"((a)[1]), "r"((a)[2]), "r"((a)[3]), "r"(b0), "r"(b1))

// ---------------- prep kernel (fused): blocks [0,16384) transpose x+p ->
// g_xt fp16 [b][d][k]; blocks [16384, 24576) build banded FT in fp16.
// FT[l,k] = cos(2*pi*l*(k-l)/1025)/sqrt(1025) for l <= k <= l+1024, else 0.
#define XT_BLOCKS 16384

__global__ void prep_kernel(const float* __restrict__ x,
                            const float* __restrict__ p,
                            const int* __restrict__ add_pos) {
    int bi = blockIdx.x;
    if (bi < XT_BLOCKS) {
        __shared__ float tile[32][33];
        int b   = bi >> 12;
        int rem = bi & 4095;
        int d0  = (rem >> 6) << 5;
        int k0  = (rem & 63) << 5;
        int ap  = *add_pos;
        const size_t base = (size_t)b * KLEN * DMODEL;

        #pragma unroll
        for (int i = threadIdx.y; i < 32; i += 8) {
            size_t g = base + (size_t)(k0 + i) * DMODEL + (d0 + threadIdx.x);
            float s = x[g];
            if (ap) s += p[g];
            tile[i][threadIdx.x] = s;
        }
        __syncthreads();
        #pragma unroll
        for (int i = threadIdx.y; i < 32; i += 8) {
            float s = tile[threadIdx.x][i];
            size_t g = base + (size_t)(d0 + i) * KLEN + (k0 + threadIdx.x);
            g_xt[g] = __float2half_rn(s);
        }
    } else {
        int idx = (bi - XT_BLOCKS) * 256 + threadIdx.y * 32 + threadIdx.x;
        int l = idx >> 11;
        int k = idx & (KLEN - 1);
        int j = k - l;
        float v = 0.0f;
        if (j >= 0 && j < FLEN) {
            int r = (l * j) % FLEN;              // fits int32
            v = cospif(2.0f * (float)r / (float)FLEN) * INV_SQRT_FLEN;
        }
        g_ft[idx] = __float2half_rn(v);
    }
}

// ---------------- banded GEMM via mma.sync, fp16 single product --------------
// Smem stage layout: A @0, B @8192 (each 128 rows x 64 B,
// 16B chunks swizzled: chunk c stored at c ^ ((row>>1)&3)).
__global__ void __launch_bounds__(NTHREADS, 2)
gemm_kernel(float* __restrict__ out) {
    extern __shared__ char smem[];
    const uint32_t sbase = smem_to_u32(smem);
    const int tid  = threadIdx.x;
    const int lane = tid & 31;
    const int wid  = tid >> 5;
    const int wm   = wid & 1;    // 2 warps in M
    const int wn   = wid >> 1;   // 4 warps in N

    const int d0 = blockIdx.x * BN;
    const int m0 = blockIdx.y * BM;
    const int b  = blockIdx.z;

    const __half* tbA = g_ft + (size_t)m0 * KLEN;
    const __half* tbB = g_xt + ((size_t)b * DMODEL + d0) * KLEN;

    // ---- stage loader: 4 x 16B cp.async per thread ----
    auto load_stage = [&](int stage, int k0) {
        const __half* bases[2] = {tbA, tbB};
        #pragma unroll
        for (int i = 0; i < 4; i++) {
            const int t   = i >> 1;                  // 0 = A, 1 = B
            const int idx = (i & 1) * 256 + tid;     // 0..511 within tile
            const int r   = idx >> 2;
            const int c   = idx & 3;
            const int csw = c ^ ((r >> 1) & 3);
            uint32_t so = sbase + stage * STAGE_BYTES + t * TILE_BYTES
                        + r * 64 + (csw << 4);
            const __half* g = bases[t] + (size_t)r * KLEN + k0 + c * 8;
            CP_ASYNC16(so, g);
        }
        CP_COMMIT();
    };

    float acc[4][4][4] = {};   // [mi][ni][4]

    load_stage(0, m0);                  // band starts at k = m0
    load_stage(1, m0 + BK);

    for (int kt = 0; kt < KITERS; kt++) {
        CP_WAIT1();                      // tile kt arrived
        __syncthreads();                 // all warps finished reading stage kt-1
        if (kt + 2 < KITERS) load_stage((kt + 2) % NSTAGES, m0 + (kt + 2) * BK);
        else                 CP_COMMIT();   // empty group keeps wait math uniform

        const uint32_t sb   = sbase + (kt % NSTAGES) * STAGE_BYTES;
        const uint32_t aoff = sb;
        const uint32_t boff = sb + TILE_BYTES;

        #pragma unroll
        for (int ks = 0; ks < 2; ks++) {
            uint32_t af[4][4];
            uint32_t bfr[2][4];
            #pragma unroll
            for (int mi = 0; mi < 4; mi++) {
                int row_s = wm * 64 + mi * 16 + (lane & 15);
                int chunk = ks * 2 + (lane >> 4);
                uint32_t addr = aoff + row_s * 64
                              + ((chunk ^ ((row_s >> 1) & 3)) << 4);
                LDSM_X4(af[mi], addr);
            }
            #pragma unroll
            for (int pr = 0; pr < 2; pr++) {
                int g8    = lane >> 3;           // 0..3 matrix select
                int ntile = pr * 2 + (g8 >> 1);
                int khalf = g8 & 1;
                int row_s = wn * 32 + ntile * 8 + (lane & 7);
                int chunk = ks * 2 + khalf;
                uint32_t addr = boff + row_s * 64
                              + ((chunk ^ ((row_s >> 1) & 3)) << 4);
                LDSM_X4(bfr[pr], addr);
            }
            #pragma unroll
            for (int mi = 0; mi < 4; mi++)
                #pragma unroll
                for (int ni = 0; ni < 4; ni++)
                    MMA16816(acc[mi][ni], af[mi],
                             bfr[ni >> 1][(ni & 1) * 2],
                             bfr[ni >> 1][(ni & 1) * 2 + 1]);
        }
    }

    // ---- epilogue: scale + float2 stores ----
    #pragma unroll
    for (int mi = 0; mi < 4; mi++) {
        #pragma unroll
        for (int ni = 0; ni < 4; ni++) {
            int row = m0 + wm * 64 + mi * 16 + (lane >> 2);
            int col = d0 + wn * 32 + ni * 8 + (lane & 3) * 2;
            float* o = out + ((size_t)b * QLEN + row) * DMODEL + col;
            float2 v0 = {acc[mi][ni][0] * SCALE_OUT, acc[mi][ni][1] * SCALE_OUT};
            float2 v1 = {acc[mi][ni][2] * SCALE_OUT, acc[mi][ni][3] * SCALE_OUT};
            *reinterpret_cast<float2*>(o) = v0;
            *reinterpret_cast<float2*>(o + 8 * DMODEL) = v1;
        }
    }
}

// ---------------- launch ----------------
extern "C" void kernel_launch(void* const* d_in, const int* in_sizes, int n_in,
                              void* d_out, int out_size) {
    const float* x = (const float*)d_in[0];
    const float* p = (const float*)d_in[1];
    // d_in[2] = qlen (fixed 1024 by problem shape), d_in[3] = add_position flag
    const int* add_pos = (const int*)d_in[3];
    float* out = (float*)d_out;

    cudaFuncSetAttribute(gemm_kernel,
                         cudaFuncAttributeMaxDynamicSharedMemorySize, SMEM_BYTES);

    prep_kernel<<<XT_BLOCKS + (QLEN * KLEN) / 256, dim3(32, 8)>>>(x, p, add_pos);
    gemm_kernel<<<dim3(DMODEL / BN, QLEN / BM, BATCH), NTHREADS, SMEM_BYTES>>>(out);
}

// round 4
// speedup vs baseline: 2.4344x; 1.1937x over previous
#include <cuda_runtime.h>
#include <cuda_fp16.h>
#include <cstdint>

// ---------------- problem constants ----------------
#define BATCH  4
#define QLEN   1024
#define KLEN   2048
#define DMODEL 2048
#define FLEN   1025

#define INV_SQRT_FLEN 0.031234752f    // 1/sqrt(1025)
#define SCALE_OUT     0.022097087f    // 1/sqrt(2048)

// GEMM tiling (mma.sync fp16)
#define BM 128
#define BN 128
#define BK 32
#define KITERS 36                     // banded K extent 1152 = 36*32
#define NTHREADS 256
#define A_TILE_BYTES (128 * 64)       // 128 m-rows x 32 fp16 (64 B)
#define B_TILE_BYTES (32 * 256)       // 32 k-rows x 128 fp16 (256 B)
#define STAGE_BYTES  (A_TILE_BYTES + B_TILE_BYTES)   // 16 KB
#define NSTAGES 4
#define SMEM_BYTES   (NSTAGES * STAGE_BYTES)         // 64 KB

// ---------------- device scratch (no allocations allowed) ----------------
__device__ __half g_ft[(size_t)QLEN * KLEN];                 // [l][k], banded
__device__ __half g_xk[(size_t)BATCH * KLEN * DMODEL];       // [b][k][d] fp16

// ---------------- PTX helpers ----------------
__device__ __forceinline__ uint32_t smem_to_u32(const void* smem_ptr) {
    uint32_t addr;
    asm("{ .reg .u64 tmp; cvta.to.shared.u64 tmp, %1; cvt.u32.u64 %0, tmp; }"
        : "=r"(addr) : "l"(smem_ptr));
    return addr;
}

#define CP_ASYNC16(dst_u32, src_ptr) \
    asm volatile("cp.async.cg.shared.global [%0], [%1], 16;" \
                 :: "r"(dst_u32), "l"(src_ptr))

#define CP_COMMIT() asm volatile("cp.async.commit_group;" ::: "memory")
#define CP_WAIT2()  asm volatile("cp.async.wait_group 2;" ::: "memory")

#define LDSM_X4(r, addr) \
    asm volatile("ldmatrix.sync.aligned.m8n8.x4.shared.b16 {%0,%1,%2,%3}, [%4];" \
        : "=r"((r)[0]), "=r"((r)[1]), "=r"((r)[2]), "=r"((r)[3]) : "r"(addr))

#define LDSM_X4_T(r, addr) \
    asm volatile("ldmatrix.sync.aligned.m8n8.x4.trans.shared.b16 {%0,%1,%2,%3}, [%4];" \
        : "=r"((r)[0]), "=r"((r)[1]), "=r"((r)[2]), "=r"((r)[3]) : "r"(addr))

#define MMA16816(c, a, b0, b1) \
    asm volatile("mma.sync.aligned.m16n8k16.row.col.f32.f16.f16.f32 " \
        "{%0,%1,%2,%3}, {%4,%5,%6,%7}, {%8,%9}, {%0,%1,%2,%3};" \
        : "+f"((c)[0]), "+f"((c)[1]), "+f"((c)[2]), "+f"((c)[3]) \
        : "r"((a)[0]), "r"((a)[1]), "r"((a)[2]), "r"((a)[3]), "r"(b0), "r"(b1))

// ---------------- prep kernel (fused) ----------------
// blocks [0, XT_BLOCKS): g_xk[b][k][d] = fp16(x (+p))   (elementwise, coalesced)
// blocks [XT_BLOCKS, +FT_BLOCKS): banded FT in fp16:
//   FT[l,k] = cos(2*pi*l*(k-l)/1025)/sqrt(1025) for l <= k <= l+1024, else 0.
#define XT_BLOCKS 16384   // 16.7M elements / (256 thr * 4 elem)
#define FT_BLOCKS 8192    // 2M elements / 256

__global__ void __launch_bounds__(256)
prep_kernel(const float* __restrict__ x, const float* __restrict__ p,
            const int* __restrict__ add_pos) {
    int bi = blockIdx.x;
    if (bi < XT_BLOCKS) {
        size_t e0 = ((size_t)bi * 256 + threadIdx.x) * 4;
        float4 xs = *reinterpret_cast<const float4*>(x + e0);
        if (*add_pos) {
            float4 ps = *reinterpret_cast<const float4*>(p + e0);
            xs.x += ps.x; xs.y += ps.y; xs.z += ps.z; xs.w += ps.w;
        }
        __half2 h0 = __floats2half2_rn(xs.x, xs.y);
        __half2 h1 = __floats2half2_rn(xs.z, xs.w);
        *reinterpret_cast<__half2*>(g_xk + e0)     = h0;
        *reinterpret_cast<__half2*>(g_xk + e0 + 2) = h1;
    } else {
        int idx = (bi - XT_BLOCKS) * 256 + threadIdx.x;
        int l = idx >> 11;
        int k = idx & (KLEN - 1);
        int j = k - l;
        float v = 0.0f;
        if (j >= 0 && j < FLEN) {
            int r = (l * j) % FLEN;              // fits int32
            v = cospif(2.0f * (float)r / (float)FLEN) * INV_SQRT_FLEN;
        }
        g_ft[idx] = __float2half_rn(v);
    }
}

// ---------------- banded GEMM via mma.sync fp16 ------------------------------
// Stage layout: A @0 (128 rows x 64 B, chunk swizzle c^((row>>1)&3)),
//               B @8192 (32 k-rows x 256 B, chunk swizzle c^(row&7)).
__global__ void __launch_bounds__(NTHREADS, 2)
gemm_kernel(float* __restrict__ out) {
    extern __shared__ char smem[];
    const uint32_t sbase = smem_to_u32(smem);
    const int tid  = threadIdx.x;
    const int lane = tid & 31;
    const int wid  = tid >> 5;
    const int wm   = wid & 1;    // 2 warps in M
    const int wn   = wid >> 1;   // 4 warps in N

    const int d0 = blockIdx.x * BN;
    const int m0 = blockIdx.y * BM;
    const int b  = blockIdx.z;

    const __half* gA = g_ft + (size_t)m0 * KLEN;                       // [m][k]
    const __half* gB = g_xk + (size_t)b * KLEN * DMODEL + d0;          // [k][d]

    // ---- stage loader: 4 x 16B cp.async per thread (A: 2, B: 2) ----
    auto load_stage = [&](int stage, int k0) {
        const uint32_t so = sbase + stage * STAGE_BYTES;
        #pragma unroll
        for (int i = 0; i < 2; i++) {          // A: 512 chunks of 16 B
            int idx = i * 256 + tid;
            int r = idx >> 2, c = idx & 3;
            int csw = c ^ ((r >> 1) & 3);
            CP_ASYNC16(so + r * 64 + (csw << 4),
                       gA + (size_t)r * KLEN + k0 + c * 8);
        }
        #pragma unroll
        for (int i = 0; i < 2; i++) {          // B: 512 chunks of 16 B
            int idx = i * 256 + tid;
            int r = idx >> 4, c = idx & 15;
            int csw = c ^ (r & 7);
            CP_ASYNC16(so + A_TILE_BYTES + r * 256 + (csw << 4),
                       gB + (size_t)(k0 + r) * DMODEL + c * 8);
        }
        CP_COMMIT();
    };

    float acc[4][4][4] = {};   // [mi][ni][4]

    load_stage(0, m0);                   // band starts at k = m0
    load_stage(1, m0 + BK);
    load_stage(2, m0 + 2 * BK);

    for (int kt = 0; kt < KITERS; kt++) {
        CP_WAIT2();                      // tile kt arrived (<=2 groups pending)
        __syncthreads();                 // everyone done reading stage kt-1
        if (kt + 3 < KITERS) load_stage((kt + 3) & 3, m0 + (kt + 3) * BK);
        else                 CP_COMMIT();   // empty group keeps wait math uniform

        const uint32_t aoff = sbase + (kt & 3) * STAGE_BYTES;
        const uint32_t boff = aoff + A_TILE_BYTES;

        #pragma unroll
        for (int ks = 0; ks < 2; ks++) {
            uint32_t af[4][4];
            uint32_t bfr[2][4];
            #pragma unroll
            for (int mi = 0; mi < 4; mi++) {   // A m16k16 frags (non-trans)
                int row_s = wm * 64 + mi * 16 + (lane & 15);
                int chunk = ks * 2 + (lane >> 4);
                uint32_t addr = aoff + row_s * 64
                              + ((chunk ^ ((row_s >> 1) & 3)) << 4);
                LDSM_X4(af[mi], addr);
            }
            #pragma unroll
            for (int pr = 0; pr < 2; pr++) {   // B k16n16 frags via trans
                int g8    = lane >> 3;          // matrix select 0..3
                int ntile = pr * 2 + (g8 >> 1);
                int khalf = g8 & 1;
                int row_s = ks * 16 + khalf * 8 + (lane & 7);   // k within tile
                int chunk = wn * 4 + ntile;                     // d/8 within 256B row
                uint32_t addr = boff + row_s * 256
                              + ((chunk ^ (row_s & 7)) << 4);
                LDSM_X4_T(bfr[pr], addr);
            }
            #pragma unroll
            for (int mi = 0; mi < 4; mi++)
                #pragma unroll
                for (int ni = 0; ni < 4; ni++)
                    MMA16816(acc[mi][ni], af[mi],
                             bfr[ni >> 1][(ni & 1) * 2],
                             bfr[ni >> 1][(ni & 1) * 2 + 1]);
        }
    }

    // ---- epilogue: scale + float2 stores ----
    #pragma unroll
    for (int mi = 0; mi < 4; mi++) {
        #pragma unroll
        for (int ni = 0; ni < 4; ni++) {
            int row = m0 + wm * 64 + mi * 16 + (lane >> 2);
            int col = d0 + wn * 32 + ni * 8 + (lane & 3) * 2;
            float* o = out + ((size_t)b * QLEN + row) * DMODEL + col;
            float2 v0 = {acc[mi][ni][0] * SCALE_OUT, acc[mi][ni][1] * SCALE_OUT};
            float2 v1 = {acc[mi][ni][2] * SCALE_OUT, acc[mi][ni][3] * SCALE_OUT};
            *reinterpret_cast<float2*>(o) = v0;
            *reinterpret_cast<float2*>(o + 8 * DMODEL) = v1;
        }
    }
}

// ---------------- launch ----------------
extern "C" void kernel_launch(void* const* d_in, const int* in_sizes, int n_in,
                              void* d_out, int out_size) {
    const float* x = (const float*)d_in[0];
    const float* p = (const float*)d_in[1];
    // d_in[2] = qlen (fixed 1024 by problem shape), d_in[3] = add_position flag
    const int* add_pos = (const int*)d_in[3];
    float* out = (float*)d_out;

    cudaFuncSetAttribute(gemm_kernel,
                         cudaFuncAttributeMaxDynamicSharedMemorySize, SMEM_BYTES);

    prep_kernel<<<XT_BLOCKS + FT_BLOCKS, 256>>>(x, p, add_pos);
    gemm_kernel<<<dim3(DMODEL / BN, QLEN / BM, BATCH), NTHREADS, SMEM_BYTES>>>(out);
}